// round 4
// baseline (speedup 1.0000x reference)
#include <cuda_runtime.h>

static constexpr int D = 128;
static constexpr int K = 8;

// Zero the scalar accumulator (d_out is poisoned to 0xAA before timing and is
// reused across graph replays, so it must be reset every kernel_launch).
__global__ void spl_zero_kernel(float* out) { *out = 0.0f; }

__global__ __launch_bounds__(256) void spl_loss_kernel(
    const float* __restrict__ emb,
    const int*   __restrict__ pair_ids,
    const int*   __restrict__ dims,
    float*       __restrict__ out,
    int n_pairs, float inv_p)
{
    const unsigned FULL = 0xFFFFFFFFu;
    const int lane = threadIdx.x & 31;
    const int wid  = threadIdx.x >> 5;       // 8 warps per block
    const int pair = blockIdx.x * 8 + wid;

    float loss = 0.0f;
    if (pair < n_pairs) {
        // Uniform per-warp load: one transaction, broadcast to all lanes.
        int2 pr = __ldg(((const int2*)pair_ids) + pair);
        const float4* r1 = (const float4*)(emb + (size_t)pr.x * D);
        const float4* r2 = (const float4*)(emb + (size_t)pr.y * D);
        float4 a = __ldg(r1 + lane);   // v1[lane*4 .. lane*4+3]
        float4 b = __ldg(r2 + lane);   // v2[lane*4 .. lane*4+3]

        int mydim = 0;
        if (lane < K) mydim = __ldg(dims + (size_t)pair * K + lane);

        // ---- polarity: lanes 0..7 fetch v1[dim], v2[dim] via shuffle ----
        int src = mydim >> 2;
        int e   = mydim & 3;
        float ax = __shfl_sync(FULL, a.x, src);
        float ay = __shfl_sync(FULL, a.y, src);
        float az = __shfl_sync(FULL, a.z, src);
        float aw = __shfl_sync(FULL, a.w, src);
        float bx = __shfl_sync(FULL, b.x, src);
        float by = __shfl_sync(FULL, b.y, src);
        float bz = __shfl_sync(FULL, b.z, src);
        float bw = __shfl_sync(FULL, b.w, src);
        float a1 = (e == 0) ? ax : (e == 1) ? ay : (e == 2) ? az : aw;
        float a2 = (e == 0) ? bx : (e == 1) ? by : (e == 2) ? bz : bw;

        float pd = 0.0f;
        if (lane < K) {
            float s   = fabsf(a1) + fabsf(a2);
            bool zero = (a1 == 0.0f) || (a2 == 0.0f);            // sign_prod == 0
            bool opp  = ((__float_as_int(a1) ^ __float_as_int(a2)) < 0); // sign bits differ
            pd = zero ? 0.1f : (opp ? -0.5f * s : s);
        }

        // ---- broadcast the 8 dims to all lanes ----
        int dv0 = __shfl_sync(FULL, mydim, 0);
        int dv1 = __shfl_sync(FULL, mydim, 1);
        int dv2 = __shfl_sync(FULL, mydim, 2);
        int dv3 = __shfl_sync(FULL, mydim, 3);
        int dv4 = __shfl_sync(FULL, mydim, 4);
        int dv5 = __shfl_sync(FULL, mydim, 5);
        int dv6 = __shfl_sync(FULL, mydim, 6);
        int dv7 = __shfl_sync(FULL, mydim, 7);

        // ---- similarity: total diff^2 minus contributions of selected dims ----
        float dx = a.x - b.x, dy = a.y - b.y, dz = a.z - b.z, dw = a.w - b.w;
        float t0 = dx * dx, t1 = dy * dy, t2 = dz * dz, t3 = dw * dw;
        int base = lane * 4;

        #define SPL_MEMBER(idx) \
            ((idx) == dv0 || (idx) == dv1 || (idx) == dv2 || (idx) == dv3 || \
             (idx) == dv4 || (idx) == dv5 || (idx) == dv6 || (idx) == dv7)
        bool m0 = SPL_MEMBER(base + 0);
        bool m1 = SPL_MEMBER(base + 1);
        bool m2 = SPL_MEMBER(base + 2);
        bool m3 = SPL_MEMBER(base + 3);
        #undef SPL_MEMBER

        float total   = t0 + t1 + t2 + t3;
        float removed = (m0 ? t0 : 0.0f) + (m1 ? t1 : 0.0f)
                      + (m2 ? t2 : 0.0f) + (m3 ? t3 : 0.0f);
        int   cntrem  = (int)m0 + (int)m1 + (int)m2 + (int)m3;

        // ---- warp reductions ----
        #pragma unroll
        for (int off = 16; off > 0; off >>= 1) {
            pd      += __shfl_xor_sync(FULL, pd,      off);
            total   += __shfl_xor_sync(FULL, total,   off);
            removed += __shfl_xor_sync(FULL, removed, off);
            cntrem  += __shfl_xor_sync(FULL, cntrem,  off);
        }

        int keep  = D - cntrem;                      // distinct-dims complement count
        float sim = (keep > 0) ? (total - removed) / (float)keep : 0.0f;
        loss = pd + 0.5f * sim;                      // POLARITY_WEIGHT=1, SIMILARITY_WEIGHT=0.5
    }

    // ---- block reduce (lane 0 of each warp) + one atomic per block ----
    __shared__ float warp_sums[8];
    if (lane == 0) warp_sums[wid] = loss;
    __syncthreads();
    if (threadIdx.x == 0) {
        float s = 0.0f;
        #pragma unroll
        for (int w = 0; w < 8; w++) s += warp_sums[w];
        atomicAdd(out, s * inv_p);
    }
}

extern "C" void kernel_launch(void* const* d_in, const int* in_sizes, int n_in,
                              void* d_out, int out_size)
{
    const float* emb      = (const float*)d_in[0];  // (VOCAB, 128) f32
    const int*   pair_ids = (const int*)  d_in[1];  // (P, 2) i32
    const int*   dims     = (const int*)  d_in[2];  // (P, 8) i32
    float*       out      = (float*)d_out;          // scalar f32

    int n_pairs = in_sizes[1] / 2;
    spl_zero_kernel<<<1, 1>>>(out);
    int blocks = (n_pairs + 7) / 8;                 // 8 warps (pairs) per 256-thread block
    spl_loss_kernel<<<blocks, 256>>>(emb, pair_ids, dims, out,
                                     n_pairs, 1.0f / (float)n_pairs);
}

// round 5
// speedup vs baseline: 1.0808x; 1.0808x over previous
#include <cuda_runtime.h>

static constexpr int D = 128;
static constexpr int K = 8;

// Zero the scalar accumulator (d_out is poisoned to 0xAA before timing and is
// reused across graph replays, so it must be reset every kernel_launch).
__global__ void spl_zero_kernel(float* out) { *out = 0.0f; }

__global__ __launch_bounds__(256) void spl_loss_kernel(
    const float* __restrict__ emb,
    const int*   __restrict__ pair_ids,
    const int*   __restrict__ dims,
    float*       __restrict__ out,
    int n_pairs, float inv_p)
{
    const unsigned FULL = 0xFFFFFFFFu;
    const int lane = threadIdx.x & 31;
    const int wid  = threadIdx.x >> 5;        // 8 warps (pairs) per block
    const int pair = blockIdx.x * 8 + wid;

    __shared__ unsigned marks[8][32];         // 128 bytes per warp: dim-membership flags
    __shared__ float    warp_sums[8];

    float c = 0.0f;
    if (pair < n_pairs) {
        // Uniform per-warp index load (one transaction, broadcast).
        int2 pr = __ldg(((const int2*)pair_ids) + pair);
        const float* row1 = emb + (size_t)pr.x * D;
        const float* row2 = emb + (size_t)pr.y * D;

        // Coalesced full-row reads: 4 x 128B wavefronts per row.
        float4 a = __ldg((const float4*)row1 + lane);
        float4 b = __ldg((const float4*)row2 + lane);

        // Mark selected dims in shared bytes; fetch polarity values directly
        // from L1 (lines are already resident from the row loads above).
        marks[wid][lane] = 0u;
        __syncwarp();
        int   mydim = 0;
        float a1 = 0.0f, a2 = 0.0f;
        if (lane < K) {
            mydim = __ldg(dims + (size_t)pair * K + lane);
            ((unsigned char*)marks[wid])[mydim] = 1;
            a1 = __ldg(row1 + mydim);
            a2 = __ldg(row2 + mydim);
        }
        __syncwarp();
        unsigned w = marks[wid][lane];        // bytes for elements lane*4 .. lane*4+3

        // ---- polarity (lanes 0..7), duplicates counted as in take_along_axis ----
        float pd = 0.0f;
        if (lane < K) {
            float s   = fabsf(a1) + fabsf(a2);
            bool zero = (a1 == 0.0f) || (a2 == 0.0f);             // sign_prod == 0
            bool opp  = ((__float_as_int(a1) ^ __float_as_int(a2)) < 0);
            pd = zero ? 0.1f : (opp ? -0.5f * s : s);
        }

        // ---- kept = sum of diff^2 over NON-selected elements (predicated FFMA) ----
        float dx = a.x - b.x, dy = a.y - b.y, dz = a.z - b.z, dw = a.w - b.w;
        float kept = 0.0f;
        if (!(w & 0x000000FFu)) kept = fmaf(dx, dx, kept);
        if (!(w & 0x0000FF00u)) kept = fmaf(dy, dy, kept);
        if (!(w & 0x00FF0000u)) kept = fmaf(dz, dz, kept);
        if (!(w & 0xFF000000u)) kept = fmaf(dw, dw, kept);

        // ---- distinct-dim count: byte-sum per lane, one REDUX across the warp ----
        unsigned cnt = (w * 0x01010101u) >> 24;     // marked bytes in this lane's word
        unsigned distinct = __reduce_add_sync(FULL, cnt);
        int keep = D - (int)distinct;               // always >= 120 here
        float invk = (keep > 0) ? __fdividef(0.5f, (float)keep) : 0.0f;

        // Single fused per-lane contribution (POLARITY_W=1, SIMILARITY_W=0.5).
        c = fmaf(kept, invk, pd);
    }

    // ---- one butterfly reduction for everything ----
    #pragma unroll
    for (int off = 16; off > 0; off >>= 1)
        c += __shfl_xor_sync(FULL, c, off);

    if (lane == 0) warp_sums[wid] = c;
    __syncthreads();
    if (threadIdx.x == 0) {
        float s = 0.0f;
        #pragma unroll
        for (int v = 0; v < 8; v++) s += warp_sums[v];
        atomicAdd(out, s * inv_p);
    }
}

extern "C" void kernel_launch(void* const* d_in, const int* in_sizes, int n_in,
                              void* d_out, int out_size)
{
    const float* emb      = (const float*)d_in[0];  // (VOCAB, 128) f32
    const int*   pair_ids = (const int*)  d_in[1];  // (P, 2) i32
    const int*   dims     = (const int*)  d_in[2];  // (P, 8) i32
    float*       out      = (float*)d_out;          // scalar f32

    int n_pairs = in_sizes[1] / 2;
    spl_zero_kernel<<<1, 1>>>(out);
    int blocks = (n_pairs + 7) / 8;                 // 8 pairs per 256-thread block
    spl_loss_kernel<<<blocks, 256>>>(emb, pair_ids, dims, out,
                                     n_pairs, 1.0f / (float)n_pairs);
}

// round 6
// speedup vs baseline: 1.4894x; 1.3781x over previous
#include <cuda_runtime.h>

static constexpr int D = 128;
static constexpr int K = 8;

// Zero the scalar accumulator (d_out is poisoned to 0xAA before timing and is
// reused across graph replays, so it must be reset every kernel_launch).
__global__ void spl_zero_kernel(float* out) { *out = 0.0f; }

// One warp processes TWO pairs: doubles per-warp memory-level parallelism
// (4 independent row gathers in flight) to hide L2/DRAM latency.
__global__ __launch_bounds__(256) void spl_loss_kernel(
    const float* __restrict__ emb,
    const int*   __restrict__ pair_ids,
    const int*   __restrict__ dims,
    float*       __restrict__ out,
    int n_pairs, float inv_p)
{
    const unsigned FULL = 0xFFFFFFFFu;
    const int lane = threadIdx.x & 31;
    const int wid  = threadIdx.x >> 5;            // 8 warps per block
    const int p0   = (blockIdx.x * 8 + wid) * 2;  // even pair index
    const int p1   = p0 + 1;

    __shared__ unsigned marks[8][64];             // 256 B/warp: [0,128)=pair0, [128,256)=pair1
    __shared__ float    warp_sums[8];

    float c = 0.0f;
    if (p0 < n_pairs) {
        const bool has1 = (p1 < n_pairs);

        // Both pairs' ids in one uniform 16B load (p0 is always even).
        int4 pr = __ldg((const int4*)pair_ids + (p0 >> 1));

        const float* r0a = emb + (size_t)pr.x * D;
        const float* r0b = emb + (size_t)pr.y * D;
        const float* r1a = emb + (size_t)pr.z * D;
        const float* r1b = emb + (size_t)pr.w * D;

        // 4 independent coalesced row reads, all in flight together.
        float4 A0 = __ldg((const float4*)r0a + lane);
        float4 B0 = __ldg((const float4*)r0b + lane);
        float4 A1 = make_float4(0.f, 0.f, 0.f, 0.f);
        float4 B1 = A1;
        if (has1) {
            A1 = __ldg((const float4*)r1a + lane);
            B1 = __ldg((const float4*)r1b + lane);
        }

        // Mark selected dims; gather polarity values (L1 hits — lines already
        // resident from the row loads). Lanes 0-7 -> pair0, lanes 8-15 -> pair1.
        marks[wid][lane]      = 0u;
        marks[wid][lane + 32] = 0u;
        __syncwarp();
        const bool pol_lane = (lane < 8) || (lane < 16 && has1);
        float g1 = 0.0f, g2 = 0.0f;
        if (pol_lane) {
            int mydim = __ldg(dims + (size_t)p0 * K + lane);  // 16 contiguous ints
            ((unsigned char*)marks[wid])[((lane >> 3) << 7) + mydim] = 1;
            const float* ra = (lane < 8) ? r0a : r1a;
            const float* rb = (lane < 8) ? r0b : r1b;
            g1 = __ldg(ra + mydim);
            g2 = __ldg(rb + mydim);
        }
        __syncwarp();
        unsigned w0 = marks[wid][lane];
        unsigned w1 = marks[wid][lane + 32];

        // ---- polarity (duplicates counted, exactly like take_along_axis) ----
        float pd = 0.0f;
        if (pol_lane) {
            float s   = fabsf(g1) + fabsf(g2);
            bool zero = (g1 == 0.0f) || (g2 == 0.0f);             // sign_prod == 0
            bool opp  = ((__float_as_int(g1) ^ __float_as_int(g2)) < 0);
            pd = zero ? 0.1f : (opp ? -0.5f * s : s);
        }

        // ---- kept diff^2 over NON-selected elements, both pairs ----
        float dx0 = A0.x - B0.x, dy0 = A0.y - B0.y, dz0 = A0.z - B0.z, dw0 = A0.w - B0.w;
        float kept0 = 0.0f;
        if (!(w0 & 0x000000FFu)) kept0 = fmaf(dx0, dx0, kept0);
        if (!(w0 & 0x0000FF00u)) kept0 = fmaf(dy0, dy0, kept0);
        if (!(w0 & 0x00FF0000u)) kept0 = fmaf(dz0, dz0, kept0);
        if (!(w0 & 0xFF000000u)) kept0 = fmaf(dw0, dw0, kept0);

        float dx1 = A1.x - B1.x, dy1 = A1.y - B1.y, dz1 = A1.z - B1.z, dw1 = A1.w - B1.w;
        float kept1 = 0.0f;
        if (!(w1 & 0x000000FFu)) kept1 = fmaf(dx1, dx1, kept1);
        if (!(w1 & 0x0000FF00u)) kept1 = fmaf(dy1, dy1, kept1);
        if (!(w1 & 0x00FF0000u)) kept1 = fmaf(dz1, dz1, kept1);
        if (!(w1 & 0xFF000000u)) kept1 = fmaf(dw1, dw1, kept1);

        // ---- distinct-dim counts (bytes summed per lane, REDUX across warp) ----
        unsigned d0 = __reduce_add_sync(FULL, (w0 * 0x01010101u) >> 24);
        unsigned d1 = __reduce_add_sync(FULL, (w1 * 0x01010101u) >> 24);
        int keep0 = D - (int)d0;                          // >= 120 always
        int keep1 = D - (int)d1;
        float invk0 = (keep0 > 0) ? __fdividef(0.5f, (float)keep0) : 0.0f;
        float invk1 = (has1 && keep1 > 0) ? __fdividef(0.5f, (float)keep1) : 0.0f;

        // Fused per-lane contribution for both pairs (POL_W=1, SIM_W=0.5).
        c = fmaf(kept0, invk0, fmaf(kept1, invk1, pd));
    }

    // ---- one butterfly reduction for everything ----
    #pragma unroll
    for (int off = 16; off > 0; off >>= 1)
        c += __shfl_xor_sync(FULL, c, off);

    if (lane == 0) warp_sums[wid] = c;
    __syncthreads();
    if (threadIdx.x == 0) {
        float s = 0.0f;
        #pragma unroll
        for (int v = 0; v < 8; v++) s += warp_sums[v];
        atomicAdd(out, s * inv_p);
    }
}

extern "C" void kernel_launch(void* const* d_in, const int* in_sizes, int n_in,
                              void* d_out, int out_size)
{
    const float* emb      = (const float*)d_in[0];  // (VOCAB, 128) f32
    const int*   pair_ids = (const int*)  d_in[1];  // (P, 2) i32
    const int*   dims     = (const int*)  d_in[2];  // (P, 8) i32
    float*       out      = (float*)d_out;          // scalar f32

    int n_pairs = in_sizes[1] / 2;
    spl_zero_kernel<<<1, 1>>>(out);
    int pairs_per_block = 16;                       // 8 warps x 2 pairs
    int blocks = (n_pairs + pairs_per_block - 1) / pairs_per_block;
    spl_loss_kernel<<<blocks, 256>>>(emb, pair_ids, dims, out,
                                     n_pairs, 1.0f / (float)n_pairs);
}

// round 8
// speedup vs baseline: 1.5268x; 1.0252x over previous
#include <cuda_runtime.h>
#include <cstdint>

static constexpr int D       = 128;
static constexpr int K       = 8;
static constexpr int WARPS   = 8;     // per block
static constexpr int ITERS   = 8;     // iterations per warp
static constexpr int PPI     = 2;     // pairs per iteration per warp
// per-warp stage buffer: 2 pairs * 2 rows * 512B = 2048 B, double-buffered
static constexpr int STAGE_FLOATS = PPI * 2 * D;          // 512 floats = 2048 B
static constexpr int STAGE_BYTES  = STAGE_FLOATS * 4;     // 2048
static constexpr int ROW_BYTES    = D * 4;                // 512
static constexpr int WARP_BUF_FLOATS = 2 * STAGE_FLOATS;  // 1024 floats (4KB)

__global__ void spl_zero_kernel(float* out) { *out = 0.0f; }

__device__ __forceinline__ void cpa16(uint32_t dst, const float* src) {
    asm volatile("cp.async.cg.shared.global [%0], [%1], 16;\n" :: "r"(dst), "l"(src));
}
__device__ __forceinline__ void cpa_commit() {
    asm volatile("cp.async.commit_group;\n" ::: "memory");
}
__device__ __forceinline__ void cpa_wait1() {
    asm volatile("cp.async.wait_group 1;\n" ::: "memory");
}

__global__ __launch_bounds__(256) void spl_loss_kernel(
    const float* __restrict__ emb,
    const int*   __restrict__ pair_ids,
    const int*   __restrict__ dims,
    float*       __restrict__ out,
    int n_pairs, float inv_p)
{
    const unsigned FULL = 0xFFFFFFFFu;
    const int lane = threadIdx.x & 31;
    const int wid  = threadIdx.x >> 5;

    __shared__ float    rows[WARPS][WARP_BUF_FLOATS];   // 32 KB
    __shared__ unsigned marks[WARPS][64];               // 2 KB
    __shared__ float    warp_sums[WARPS];

    const int   warp_global = blockIdx.x * WARPS + wid;
    const int   base        = warp_global * (PPI * ITERS);   // first pair (even)
    float*      mybuf       = rows[wid];
    uint32_t    sb          = (uint32_t)__cvta_generic_to_shared(mybuf) + lane * 16;

    const int   id4_max  = (n_pairs >> 1) - 1;          // last valid int4 index
    const long  dim_max  = (long)n_pairs * K - 1;

    float c = 0.0f;
    if (base < n_pairs) {
        // ---- prefetch helpers (index clamped; use guarded by validity) ----
        auto load_ids = [&](int i) -> int4 {
            int idx = warp_global * ITERS + i;
            if (idx > id4_max) idx = id4_max;
            return __ldg((const int4*)pair_ids + idx);
        };
        auto load_dim = [&](int i) -> int {
            long idx = (long)(base + PPI * i) * K + lane;   // lanes 0..15 used
            if (idx > dim_max) idx = dim_max;
            return __ldg(dims + idx);
        };
        auto issue_stage = [&](int s, int4 pr, bool v0, bool v1) {
            // rows are ROW_BYTES (512B) apart within one STAGE_BYTES (2048B) stage
            uint32_t dst = sb + (uint32_t)s * STAGE_BYTES;
            if (v0) {
                cpa16(dst,                emb + (size_t)pr.x * D + lane * 4);
                cpa16(dst + ROW_BYTES,    emb + (size_t)pr.y * D + lane * 4);
            }
            if (v1) {
                cpa16(dst + 2 * ROW_BYTES, emb + (size_t)pr.z * D + lane * 4);
                cpa16(dst + 3 * ROW_BYTES, emb + (size_t)pr.w * D + lane * 4);
            }
        };
        auto valid = [&](int i, int sub) { return base + PPI * i + sub < n_pairs; };

        // ---- prologue ----
        int4 id_q[2];
        int  dim_q[4];
        id_q[0]  = load_ids(0);
        dim_q[0] = load_dim(0);
        issue_stage(0, id_q[0], valid(0, 0), valid(0, 1));
        cpa_commit();
        id_q[1]  = load_ids(1);
        dim_q[1] = load_dim(1);

        #pragma unroll
        for (int i = 0; i < ITERS; i++) {
            // 1) issue prefetch for iter i+1 (ids already resident, latency hidden)
            if (i + 1 < ITERS)
                issue_stage((i + 1) & 1, id_q[(i + 1) & 1], valid(i + 1, 0), valid(i + 1, 1));
            cpa_commit();   // always commit -> uniform group accounting

            // 2) start loads for iter i+2 (consumed one/two iterations later)
            if (i + 2 < ITERS) {
                id_q[i & 1]        = load_ids(i + 2);
                dim_q[(i + 2) & 3] = load_dim(i + 2);
            }

            // 3) wait for stage i, then compute from smem
            cpa_wait1();
            __syncwarp();

            const float* buf = mybuf + (i & 1) * STAGE_FLOATS;
            const bool v0 = valid(i, 0);
            const bool v1 = valid(i, 1);

            marks[wid][lane]      = 0u;
            marks[wid][lane + 32] = 0u;
            __syncwarp();
            const int  mydim    = dim_q[i & 3];
            const bool pol_lane = (lane < 8) ? v0 : (lane < 16 && v1);
            float g1 = 0.0f, g2 = 0.0f;
            if (pol_lane) {
                int rs = (lane >> 3) * 256;                 // pair select within stage
                ((unsigned char*)marks[wid])[((lane >> 3) << 7) + mydim] = 1;
                g1 = buf[rs + mydim];
                g2 = buf[rs + 128 + mydim];
            }
            __syncwarp();
            unsigned w0 = marks[wid][lane];
            unsigned w1 = marks[wid][lane + 32];

            // polarity (duplicates counted, sign_prod==0 iff either value is +-0)
            if (pol_lane) {
                float s   = fabsf(g1) + fabsf(g2);
                bool zero = (g1 == 0.0f) || (g2 == 0.0f);
                bool opp  = ((__float_as_int(g1) ^ __float_as_int(g2)) < 0);
                c += zero ? 0.1f : (opp ? -0.5f * s : s);
            }

            // distinct-dim counts (warp-collective: run unconditionally)
            unsigned d0 = __reduce_add_sync(FULL, (w0 * 0x01010101u) >> 24);
            unsigned d1 = __reduce_add_sync(FULL, (w1 * 0x01010101u) >> 24);

            if (v0) {
                float4 A = ((const float4*)buf)[lane];
                float4 B = ((const float4*)(buf + 128))[lane];
                float dx = A.x - B.x, dy = A.y - B.y, dz = A.z - B.z, dw = A.w - B.w;
                float kept = 0.0f;
                if (!(w0 & 0x000000FFu)) kept = fmaf(dx, dx, kept);
                if (!(w0 & 0x0000FF00u)) kept = fmaf(dy, dy, kept);
                if (!(w0 & 0x00FF0000u)) kept = fmaf(dz, dz, kept);
                if (!(w0 & 0xFF000000u)) kept = fmaf(dw, dw, kept);
                int keep = D - (int)d0;
                c = fmaf(kept, (keep > 0) ? __fdividef(0.5f, (float)keep) : 0.0f, c);
            }
            if (v1) {
                float4 A = ((const float4*)(buf + 256))[lane];
                float4 B = ((const float4*)(buf + 384))[lane];
                float dx = A.x - B.x, dy = A.y - B.y, dz = A.z - B.z, dw = A.w - B.w;
                float kept = 0.0f;
                if (!(w1 & 0x000000FFu)) kept = fmaf(dx, dx, kept);
                if (!(w1 & 0x0000FF00u)) kept = fmaf(dy, dy, kept);
                if (!(w1 & 0x00FF0000u)) kept = fmaf(dz, dz, kept);
                if (!(w1 & 0xFF000000u)) kept = fmaf(dw, dw, kept);
                int keep = D - (int)d1;
                c = fmaf(kept, (keep > 0) ? __fdividef(0.5f, (float)keep) : 0.0f, c);
            }
            __syncwarp();   // stage reuse safety before next cp.async overwrites it
        }
    }

    // ---- warp butterfly + block reduce + one atomic per block ----
    #pragma unroll
    for (int off = 16; off > 0; off >>= 1)
        c += __shfl_xor_sync(FULL, c, off);
    if (lane == 0) warp_sums[wid] = c;
    __syncthreads();
    if (threadIdx.x == 0) {
        float s = 0.0f;
        #pragma unroll
        for (int v = 0; v < WARPS; v++) s += warp_sums[v];
        atomicAdd(out, s * inv_p);
    }
}

extern "C" void kernel_launch(void* const* d_in, const int* in_sizes, int n_in,
                              void* d_out, int out_size)
{
    const float* emb      = (const float*)d_in[0];  // (VOCAB, 128) f32
    const int*   pair_ids = (const int*)  d_in[1];  // (P, 2) i32
    const int*   dims     = (const int*)  d_in[2];  // (P, 8) i32
    float*       out      = (float*)d_out;          // scalar f32

    int n_pairs = in_sizes[1] / 2;
    spl_zero_kernel<<<1, 1>>>(out);

    int pairs_per_warp  = PPI * ITERS;                       // 16
    int warps_needed    = (n_pairs + pairs_per_warp - 1) / pairs_per_warp;
    int blocks          = (warps_needed + WARPS - 1) / WARPS;
    spl_loss_kernel<<<blocks, 256>>>(emb, pair_ids, dims, out,
                                     n_pairs, 1.0f / (float)n_pairs);
}